// round 12
// baseline (speedup 1.0000x reference)
#include <cuda_runtime.h>
#include <cuda_bf16.h>

#define WARPS_PER_BLOCK 8
#define NT 32
#define MC 4
#define NITER_MAX 64
#define LOG2E 1.4426950408889634f

union f2u { float2 f; unsigned long long u; };

static __device__ __forceinline__ float2 fma2(float2 a, float2 b, float2 c) {
    f2u A, Bv, C, D; A.f = a; Bv.f = b; C.f = c;
    asm("fma.rn.f32x2 %0, %1, %2, %3;" : "=l"(D.u) : "l"(A.u), "l"(Bv.u), "l"(C.u));
    return D.f;
}
static __device__ __forceinline__ float2 mul2(float2 a, float2 b) {
    f2u A, Bv, D; A.f = a; Bv.f = b;
    asm("mul.rn.f32x2 %0, %1, %2;" : "=l"(D.u) : "l"(A.u), "l"(Bv.u));
    return D.f;
}
static __device__ __forceinline__ float2 add2(float2 a, float2 b) {
    f2u A, Bv, D; A.f = a; Bv.f = b;
    asm("add.rn.f32x2 %0, %1, %2;" : "=l"(D.u) : "l"(A.u), "l"(Bv.u));
    return D.f;
}
static __device__ __forceinline__ float rcp_fast(float x) {
    float r; asm("rcp.approx.f32 %0, %1;" : "=f"(r) : "f"(x)); return r;
}

// TWO batch elements per warp (A/B), interleaved for ILP: the two serial
// recurrences are independent, so each fills the other's stall windows.
// Quad-split HH ownership per batch: lane (m = lane&7, q = lane>>3) holds
// cols [8q,8q+8) of rows {m,m+8,m+16,m+24} as 16 float2 per batch.
// xt broadcast via smem row + one syncwarp (R10 scheme; SHFL bcast regressed).
__global__ void __launch_bounds__(WARPS_PER_BLOCK * 32, 2)
cmdnet_kernel(const float* __restrict__ yt,
              const float* __restrict__ Ht,
              const float* __restrict__ sigmat0,
              const float* __restrict__ m_c,
              const float* __restrict__ alpha,
              const float* __restrict__ taui,
              const float* __restrict__ delta,
              float* __restrict__ out,
              int B, int NR, int NITER)
{
    __shared__ __align__(16) float4 s_lasc[NITER_MAX];  // la_j * scale_it * log2e
    __shared__ __align__(16) float4 s_p1[NITER_MAX];    // {-sc, -sc, -ta, d*log2e}
    __shared__ float s_la[MC];
    __shared__ float s_tauN, s_tauNl2;
    __shared__ __align__(16) float s_stage[WARPS_PER_BLOCK][2][NT];
    __shared__ __align__(16) float s_xt[2][WARPS_PER_BLOCK][2][NT];

    const int tid   = threadIdx.x;
    const int wslot = tid >> 5;
    const int lane  = tid & 31;
    const int m     = lane & 7;         // row-group member
    const int q     = lane >> 3;        // column-quad

    if (tid < NITER) {
        float ta = fabsf(taui[tid]);
        float scale_raw = (tid == 0) ? 1.0f : ta;     // first_iter softmax scale = 1
        float sc = scale_raw * LOG2E;
        float4 l;
        l.x = logf(alpha[0]) * sc;
        l.y = logf(alpha[1]) * sc;
        l.z = logf(alpha[2]) * sc;
        l.w = logf(alpha[3]) * sc;
        s_lasc[tid] = l;
        s_p1[tid] = make_float4(-scale_raw, -scale_raw, -ta, delta[tid] * LOG2E);
    }
    if (tid < MC) s_la[tid] = logf(alpha[tid]);
    if (tid == 0) {
        float tn = fabsf(taui[NITER]);
        s_tauN   = tn;
        s_tauNl2 = tn * LOG2E;
    }
    __syncthreads();

    const int bA = (blockIdx.x * WARPS_PER_BLOCK + wslot) * 2;
    const int bB = bA + 1;
    if (bA >= B) return;
    const bool hasB = (bB < B);
    const int bBc = hasB ? bB : bA;

    // ---------------- Phase 1 (batch A, then batch B) ----------------
    float2 hhqA[4][4], hhqB[4][4];
    float yHA = 0.0f, yHB = 0.0f;

    #pragma unroll
    for (int j = 0; j < 4; j++)
        #pragma unroll
        for (int c = 0; c < 4; c++) {
            hhqA[j][c] = make_float2(0.0f, 0.0f);
            hhqB[j][c] = make_float2(0.0f, 0.0f);
        }

    for (int pass = 0; pass < 2; pass++) {
        const int bb = pass ? bBc : bA;
        const float* Hb = Ht + (size_t)bb * NR * NT;
        const float* yb = yt + (size_t)bb * NR;
        float yH = 0.0f;
        float2 (*hhq)[4] = pass ? hhqB : hhqA;

        for (int r0 = 0; r0 < NR; r0 += 2) {
            float h0 = Hb[(r0 + 0) * NT + lane];         // own column (coalesced)
            float h1 = Hb[(r0 + 1) * NT + lane];
            s_stage[wslot][0][lane] = h0;
            s_stage[wslot][1][lane] = h1;
            yH = fmaf(yb[r0 + 0], h0, yH);               // row = lane
            yH = fmaf(yb[r0 + 1], h1, yH);
            __syncwarp();
            #pragma unroll
            for (int rr = 0; rr < 2; rr++) {
                float4 va = *reinterpret_cast<const float4*>(&s_stage[wslot][rr][8 * q]);
                float4 vb = *reinterpret_cast<const float4*>(&s_stage[wslot][rr][8 * q + 4]);
                #pragma unroll
                for (int j = 0; j < 4; j++) {
                    float hr = s_stage[wslot][rr][m + 8 * j];
                    const float2 h2 = make_float2(hr, hr);
                    hhq[j][0] = fma2(h2, make_float2(va.x, va.y), hhq[j][0]);
                    hhq[j][1] = fma2(h2, make_float2(va.z, va.w), hhq[j][1]);
                    hhq[j][2] = fma2(h2, make_float2(vb.x, vb.y), hhq[j][2]);
                    hhq[j][3] = fma2(h2, make_float2(vb.z, vb.w), hhq[j][3]);
                }
            }
            __syncwarp();
        }
        if (pass) yHB = yH; else yHA = yH;
    }

    // ---------------- Phase 2: 64 iterations, dual-chain ----------------
    float2 m2[2];
    m2[0] = make_float2(m_c[0], m_c[1]);
    m2[1] = make_float2(m_c[2], m_c[3]);

    float2 GnA[2] = {make_float2(0.f, 0.f), make_float2(0.f, 0.f)};
    float2 GnB[2] = {make_float2(0.f, 0.f), make_float2(0.f, 0.f)};
    float sA, sB;
    { float s = sigmat0[bA];  sA = s * s; }
    { float s = sigmat0[bBc]; sB = s * s; }
    const float2 sig2A  = make_float2(sA, sA),  nsig2A = make_float2(-sA, -sA);
    const float2 sig2B  = make_float2(sB, sB),  nsig2B = make_float2(-sB, -sB);

    const bool qb0 = (q & 1) != 0;
    const bool qb1 = (q & 2) != 0;

    float eA0, eA1, eA2, eA3, eB0, eB1, eB2, eB3;
    float invA = 0.f, invB = 0.f, xtA = 0.f, xtB = 0.f;

    #pragma unroll 2
    for (int it = 0; it < NITER; it++) {
        const float4 lasc = s_lasc[it];
        const float4 p    = s_p1[it];     // {-sc, -sc, -ta, d*log2e}
        const float2 sc2  = make_float2(p.x, p.y);
        const int buf = it & 1;

        // barrier exps first (loop-carried only) — 8 MUFU launch together
        const float2 egA0 = make_float2(exp2f(GnA[0].x), exp2f(GnA[0].y));
        const float2 egA1 = make_float2(exp2f(GnA[1].x), exp2f(GnA[1].y));
        const float2 egB0 = make_float2(exp2f(GnB[0].x), exp2f(GnB[0].y));
        const float2 egB1 = make_float2(exp2f(GnB[1].x), exp2f(GnB[1].y));
        float2 tA0 = fma2(nsig2A, egA0, sig2A);
        float2 tA1 = fma2(nsig2A, egA1, sig2A);
        float2 tB0 = fma2(nsig2B, egB0, sig2B);
        float2 tB1 = fma2(nsig2B, egB1, sig2B);

        // max-free softmax, both chains interleaved
        float2 zA0 = fma2(sc2, GnA[0], make_float2(lasc.x, lasc.y));
        float2 zA1 = fma2(sc2, GnA[1], make_float2(lasc.z, lasc.w));
        float2 zB0 = fma2(sc2, GnB[0], make_float2(lasc.x, lasc.y));
        float2 zB1 = fma2(sc2, GnB[1], make_float2(lasc.z, lasc.w));
        eA0 = exp2f(zA0.x); eA1 = exp2f(zA0.y); eA2 = exp2f(zA1.x); eA3 = exp2f(zA1.y);
        eB0 = exp2f(zB0.x); eB1 = exp2f(zB0.y); eB2 = exp2f(zB1.x); eB3 = exp2f(zB1.y);
        float sumA = (eA0 + eA1) + (eA2 + eA3);
        float sumB = (eB0 + eB1) + (eB2 + eB3);
        invA = rcp_fast(sumA);
        invB = rcp_fast(sumB);

        float emA = eA0 * m2[0].x;
        emA = fmaf(eA1, m2[0].y, emA);
        emA = fmaf(eA2, m2[1].x, emA);
        emA = fmaf(eA3, m2[1].y, emA);
        xtA = emA * invA;
        float emB = eB0 * m2[0].x;
        emB = fmaf(eB1, m2[0].y, emB);
        emB = fmaf(eB2, m2[1].x, emB);
        emB = fmaf(eB3, m2[1].y, emB);
        xtB = emB * invB;

        // share xt (both batches), one syncwarp
        s_xt[buf][wslot][0][lane] = xtA;
        s_xt[buf][wslot][1][lane] = xtB;
        __syncwarp();

        float4 vA0 = *reinterpret_cast<const float4*>(&s_xt[buf][wslot][0][8 * q]);
        float4 vA1 = *reinterpret_cast<const float4*>(&s_xt[buf][wslot][0][8 * q + 4]);
        float4 vB0 = *reinterpret_cast<const float4*>(&s_xt[buf][wslot][1][8 * q]);
        float4 vB1 = *reinterpret_cast<const float4*>(&s_xt[buf][wslot][1][8 * q + 4]);
        const float2 xA0 = make_float2(vA0.x, vA0.y), xA1 = make_float2(vA0.z, vA0.w);
        const float2 xA2 = make_float2(vA1.x, vA1.y), xA3 = make_float2(vA1.z, vA1.w);
        const float2 xB0 = make_float2(vB0.x, vB0.y), xB1 = make_float2(vB0.z, vB0.w);
        const float2 xB2 = make_float2(vB1.x, vB1.y), xB3 = make_float2(vB1.z, vB1.w);

        float PA[4], PB[4];
        #pragma unroll
        for (int j = 0; j < 4; j++) {
            float2 a = mul2(xA0, hhqA[j][0]);
            a = fma2(xA1, hhqA[j][1], a);
            a = fma2(xA2, hhqA[j][2], a);
            a = fma2(xA3, hhqA[j][3], a);
            PA[j] = a.x + a.y;
            float2 bacc = mul2(xB0, hhqB[j][0]);
            bacc = fma2(xB1, hhqB[j][1], bacc);
            bacc = fma2(xB2, hhqB[j][2], bacc);
            bacc = fma2(xB3, hhqB[j][3], bacc);
            PB[j] = bacc.x + bacc.y;
        }
        // reduce-scatter butterflies, A and B interleaved (independent SHFLs)
        float gA0 = qb0 ? PA[0] : PA[1];
        float gA1 = qb0 ? PA[2] : PA[3];
        float kA0 = qb0 ? PA[1] : PA[0];
        float kA1 = qb0 ? PA[3] : PA[2];
        float gB0 = qb0 ? PB[0] : PB[1];
        float gB1 = qb0 ? PB[2] : PB[3];
        float kB0 = qb0 ? PB[1] : PB[0];
        float kB1 = qb0 ? PB[3] : PB[2];
        float SA0 = kA0 + __shfl_xor_sync(0xFFFFFFFFu, gA0, 8);
        float SA1 = kA1 + __shfl_xor_sync(0xFFFFFFFFu, gA1, 8);
        float SB0 = kB0 + __shfl_xor_sync(0xFFFFFFFFu, gB0, 8);
        float SB1 = kB1 + __shfl_xor_sync(0xFFFFFFFFu, gB1, 8);
        float gA2 = qb1 ? SA0 : SA1;
        float kA2 = qb1 ? SA1 : SA0;
        float gB2 = qb1 ? SB0 : SB1;
        float kB2 = qb1 ? SB1 : SB0;
        float accA = kA2 + __shfl_xor_sync(0xFFFFFFFFu, gA2, 16);
        float accB = kB2 + __shfl_xor_sync(0xFFFFFFFFu, gB2, 16);

        // state updates
        const float cA  = (yHA - accA) * p.z;
        const float ciA = cA * invA;
        const float cB  = (yHB - accB) * p.z;
        const float ciB = cB * invB;
        const float2 dl2 = make_float2(p.w, p.w);
        {
            const float2 ci2  = make_float2(ciA, ciA);
            const float2 nxt2 = make_float2(-xtA, -xtA);
            float2 d0 = add2(m2[0], nxt2);
            float2 d1 = add2(m2[1], nxt2);
            float2 w0 = mul2(make_float2(eA0, eA1), d0);
            float2 w1 = mul2(make_float2(eA2, eA3), d1);
            GnA[0] = fma2(dl2, fma2(ci2, w0, tA0), GnA[0]);
            GnA[1] = fma2(dl2, fma2(ci2, w1, tA1), GnA[1]);
        }
        {
            const float2 ci2  = make_float2(ciB, ciB);
            const float2 nxt2 = make_float2(-xtB, -xtB);
            float2 d0 = add2(m2[0], nxt2);
            float2 d1 = add2(m2[1], nxt2);
            float2 w0 = mul2(make_float2(eB0, eB1), d0);
            float2 w1 = mul2(make_float2(eB2, eB3), d1);
            GnB[0] = fma2(dl2, fma2(ci2, w0, tB0), GnB[0]);
            GnB[1] = fma2(dl2, fma2(ci2, w1, tB1), GnB[1]);
        }
    }

    // ---------------- Final layer + write out (both batches) ----------------
    const float tl2 = s_tauNl2, tn = s_tauN;
    const float2 ntn2 = make_float2(-tn, -tn);
    const float2 laf0 = make_float2(s_la[0] * tl2, s_la[1] * tl2);
    const float2 laf1 = make_float2(s_la[2] * tl2, s_la[3] * tl2);

    #pragma unroll
    for (int pass = 0; pass < 2; pass++) {
        if (pass && !hasB) break;
        float2* Gn = pass ? GnB : GnA;
        const int bb = pass ? bB : bA;
        float2 z0 = fma2(ntn2, Gn[0], laf0);
        float2 z1 = fma2(ntn2, Gn[1], laf1);
        float e0 = exp2f(z0.x), e1 = exp2f(z0.y);
        float e2 = exp2f(z1.x), e3 = exp2f(z1.y);
        float sum = (e0 + e1) + (e2 + e3);
        float iv = __fdividef(1.0f, sum);
        float f0 = e0 * iv, f1 = e1 * iv, f2 = e2 * iv, f3 = e3 * iv;
        float em = f0 * m2[0].x;
        em = fmaf(f1, m2[0].y, em);
        em = fmaf(f2, m2[1].x, em);
        em = fmaf(f3, m2[1].y, em);
        const size_t base = (size_t)bb * NT + lane;
        float4 o; o.x = f0; o.y = f1; o.z = f2; o.w = f3;
        *reinterpret_cast<float4*>(&out[base * MC]) = o;
        out[(size_t)B * NT * MC + base] = em;
    }
}

extern "C" void kernel_launch(void* const* d_in, const int* in_sizes, int n_in,
                              void* d_out, int out_size)
{
    const float* yt     = (const float*)d_in[0];
    const float* Ht     = (const float*)d_in[1];
    const float* sig    = (const float*)d_in[2];
    const float* m      = (const float*)d_in[3];
    const float* alpha  = (const float*)d_in[4];
    const float* taui   = (const float*)d_in[5];
    const float* delta  = (const float*)d_in[6];

    const int B     = in_sizes[2];
    const int NR    = in_sizes[0] / B;
    const int NITER = in_sizes[6];

    const int batches_per_block = WARPS_PER_BLOCK * 2;
    const int blocks = (B + batches_per_block - 1) / batches_per_block;
    cmdnet_kernel<<<blocks, WARPS_PER_BLOCK * 32>>>(
        yt, Ht, sig, m, alpha, taui, delta, (float*)d_out, B, NR, NITER);
}

// round 13
// speedup vs baseline: 1.4308x; 1.4308x over previous
#include <cuda_runtime.h>
#include <cuda_bf16.h>

#define WARPS_PER_BLOCK 8
#define NT 32
#define MC 4
#define NITER_MAX 64
#define LOG2E 1.4426950408889634f

union f2u { float2 f; unsigned long long u; };

static __device__ __forceinline__ float2 fma2(float2 a, float2 b, float2 c) {
    f2u A, Bv, C, D; A.f = a; Bv.f = b; C.f = c;
    asm("fma.rn.f32x2 %0, %1, %2, %3;" : "=l"(D.u) : "l"(A.u), "l"(Bv.u), "l"(C.u));
    return D.f;
}
static __device__ __forceinline__ float2 mul2(float2 a, float2 b) {
    f2u A, Bv, D; A.f = a; Bv.f = b;
    asm("mul.rn.f32x2 %0, %1, %2;" : "=l"(D.u) : "l"(A.u), "l"(Bv.u));
    return D.f;
}
static __device__ __forceinline__ float rcp_fast(float x) {
    float r; asm("rcp.approx.f32 %0, %1;" : "=f"(r) : "f"(x)); return r;
}

// One warp per batch element. Quad-split HH ownership: lane (m = lane&7,
// q = lane>>3) holds cols [8q,8q+8) of rows {m,m+8,m+16,m+24} as 16 float2.
// FFMA2 only where operands are naturally paired (dot + HH build); all
// scalar-broadcast arithmetic stays scalar to avoid pair-marshaling MOVs.
__global__ void __launch_bounds__(WARPS_PER_BLOCK * 32, 4)
cmdnet_kernel(const float* __restrict__ yt,
              const float* __restrict__ Ht,
              const float* __restrict__ sigmat0,
              const float* __restrict__ m_c,
              const float* __restrict__ alpha,
              const float* __restrict__ taui,
              const float* __restrict__ delta,
              float* __restrict__ out,
              int B, int NR, int NITER)
{
    __shared__ __align__(16) float4 s_lasc[NITER_MAX];  // la_j * scale_it * log2e
    __shared__ __align__(16) float4 s_p1[NITER_MAX];    // {-sc, -sc, -ta, d*log2e}
    __shared__ float s_la[MC];
    __shared__ float s_tauN, s_tauNl2;
    __shared__ __align__(16) float s_stage[2][WARPS_PER_BLOCK][2][NT];
    __shared__ __align__(16) float s_xt[2][WARPS_PER_BLOCK][NT];

    const int tid   = threadIdx.x;
    const int wslot = tid >> 5;
    const int lane  = tid & 31;
    const int m     = lane & 7;         // row-group member
    const int q     = lane >> 3;        // column-quad

    if (tid < NITER) {
        float ta = fabsf(taui[tid]);
        float scale_raw = (tid == 0) ? 1.0f : ta;     // first_iter softmax scale = 1
        float sc = scale_raw * LOG2E;
        float4 l;
        l.x = logf(alpha[0]) * sc;
        l.y = logf(alpha[1]) * sc;
        l.z = logf(alpha[2]) * sc;
        l.w = logf(alpha[3]) * sc;
        s_lasc[tid] = l;
        s_p1[tid] = make_float4(-scale_raw, -scale_raw, -ta, delta[tid] * LOG2E);
    }
    if (tid < MC) s_la[tid] = logf(alpha[tid]);
    if (tid == 0) {
        float tn = fabsf(taui[NITER]);
        s_tauN   = tn;
        s_tauNl2 = tn * LOG2E;
    }
    __syncthreads();

    const int b = blockIdx.x * WARPS_PER_BLOCK + wslot;
    if (b >= B) return;

    const float* Hb = Ht + (size_t)b * NR * NT;
    const float* yb = yt + (size_t)b * NR;

    // ---------------- Phase 1: quad-split HH + per-row yH ----------------
    // hhq[j][c] = HH[m+8j][8q+2c .. 8q+2c+1]; double-buffered stage ->
    // one syncwarp per 2-row group (WAR separated by intervening sync).
    float2 hhq[4][4];
    #pragma unroll
    for (int j = 0; j < 4; j++)
        #pragma unroll
        for (int c = 0; c < 4; c++) hhq[j][c] = make_float2(0.0f, 0.0f);
    float yH = 0.0f;

    for (int g = 0; g < NR / 2; g++) {
        const int r0  = g * 2;
        const int buf = g & 1;
        float h0 = Hb[(r0 + 0) * NT + lane];             // own column (coalesced)
        float h1 = Hb[(r0 + 1) * NT + lane];
        s_stage[buf][wslot][0][lane] = h0;
        s_stage[buf][wslot][1][lane] = h1;
        yH = fmaf(yb[r0 + 0], h0, yH);                   // row = lane
        yH = fmaf(yb[r0 + 1], h1, yH);
        __syncwarp();
        #pragma unroll
        for (int rr = 0; rr < 2; rr++) {
            float4 va = *reinterpret_cast<const float4*>(&s_stage[buf][wslot][rr][8 * q]);
            float4 vb = *reinterpret_cast<const float4*>(&s_stage[buf][wslot][rr][8 * q + 4]);
            #pragma unroll
            for (int j = 0; j < 4; j++) {
                float hr = s_stage[buf][wslot][rr][m + 8 * j];
                const float2 h2 = make_float2(hr, hr);
                hhq[j][0] = fma2(h2, make_float2(va.x, va.y), hhq[j][0]);
                hhq[j][1] = fma2(h2, make_float2(va.z, va.w), hhq[j][1]);
                hhq[j][2] = fma2(h2, make_float2(vb.x, vb.y), hhq[j][2]);
                hhq[j][3] = fma2(h2, make_float2(vb.z, vb.w), hhq[j][3]);
            }
        }
    }

    // ---------------- Phase 2: 64 iterations ----------------
    float mj0 = m_c[0], mj1 = m_c[1], mj2 = m_c[2], mj3 = m_c[3];

    float Gn0 = 0.f, Gn1 = 0.f, Gn2v = 0.f, Gn3 = 0.f;   // -G * log2e
    float sig2;
    { float s = sigmat0[b]; sig2 = s * s; }

    const bool qb0 = (q & 1) != 0;      // butterfly selectors
    const bool qb1 = (q & 2) != 0;

    float e0, e1, e2, e3;
    float inv = 0.0f, xt = 0.0f;

    #pragma unroll 2
    for (int it = 0; it < NITER; it++) {
        const float4 lasc = s_lasc[it];
        const float4 p    = s_p1[it];     // {-sc, -sc, -ta, d*log2e}
        const float nsc   = p.x;
        const int buf = it & 1;

        // barrier term first (depends only on loop-carried Gn)
        float eg0 = exp2f(Gn0), eg1 = exp2f(Gn1);
        float eg2 = exp2f(Gn2v), eg3 = exp2f(Gn3);
        float t0 = fmaf(-sig2, eg0, sig2);
        float t1 = fmaf(-sig2, eg1, sig2);
        float t2 = fmaf(-sig2, eg2, sig2);
        float t3 = fmaf(-sig2, eg3, sig2);

        // max-free softmax in log2 domain (scalar: no pair marshaling)
        e0 = exp2f(fmaf(nsc, Gn0, lasc.x));
        e1 = exp2f(fmaf(nsc, Gn1, lasc.y));
        e2 = exp2f(fmaf(nsc, Gn2v, lasc.z));
        e3 = exp2f(fmaf(nsc, Gn3, lasc.w));
        float sum = (e0 + e1) + (e2 + e3);
        inv = rcp_fast(sum);

        float em = e0 * mj0;
        em = fmaf(e1, mj1, em);
        em = fmaf(e2, mj2, em);
        em = fmaf(e3, mj3, em);
        xt = em * inv;                   // soft symbol for row = lane

        // share xt, then quad-split dot: 2 LDS.128 + 16 FFMA2 + butterfly
        s_xt[buf][wslot][lane] = xt;
        __syncwarp();
        float4 v0 = *reinterpret_cast<const float4*>(&s_xt[buf][wslot][8 * q]);
        float4 v1 = *reinterpret_cast<const float4*>(&s_xt[buf][wslot][8 * q + 4]);
        const float2 xv0 = make_float2(v0.x, v0.y);
        const float2 xv1 = make_float2(v0.z, v0.w);
        const float2 xv2 = make_float2(v1.x, v1.y);
        const float2 xv3 = make_float2(v1.z, v1.w);
        float P[4];
        #pragma unroll
        for (int j = 0; j < 4; j++) {
            float2 a = mul2(xv0, hhq[j][0]);
            a = fma2(xv1, hhq[j][1], a);
            a = fma2(xv2, hhq[j][2], a);
            a = fma2(xv3, hhq[j][3], a);
            P[j] = a.x + a.y;            // partial dot of row m+8j over my 8 cols
        }
        // reduce-scatter: stage 1 (xor 8) over q-bit0, stage 2 (xor 16) over q-bit1
        float give0 = qb0 ? P[0] : P[1];
        float give1 = qb0 ? P[2] : P[3];
        float keep0 = qb0 ? P[1] : P[0];
        float keep1 = qb0 ? P[3] : P[2];
        float S0 = keep0 + __shfl_xor_sync(0xFFFFFFFFu, give0, 8);
        float S1 = keep1 + __shfl_xor_sync(0xFFFFFFFFu, give1, 8);
        float give2 = qb1 ? S0 : S1;
        float keep2 = qb1 ? S1 : S0;
        float acc = keep2 + __shfl_xor_sync(0xFFFFFFFFu, give2, 16); // row = lane

        // grad + state update (scalar)
        const float c  = (yH - acc) * p.z;       // = ta*(acc - yH)
        const float ci = c * inv;
        const float dl = p.w;
        float w0 = e0 * (mj0 - xt);
        float w1 = e1 * (mj1 - xt);
        float w2 = e2 * (mj2 - xt);
        float w3 = e3 * (mj3 - xt);
        Gn0  = fmaf(dl, fmaf(ci, w0, t0), Gn0);
        Gn1  = fmaf(dl, fmaf(ci, w1, t1), Gn1);
        Gn2v = fmaf(dl, fmaf(ci, w2, t2), Gn2v);
        Gn3  = fmaf(dl, fmaf(ci, w3, t3), Gn3);
    }

    // ---------------- Final layer: max-free softmax + soft symbol ------------
    float f0, f1, f2, f3;
    {
        const float tl2 = s_tauNl2, tn = s_tauN;
        e0 = exp2f(fmaf(-tn, Gn0,  s_la[0] * tl2));
        e1 = exp2f(fmaf(-tn, Gn1,  s_la[1] * tl2));
        e2 = exp2f(fmaf(-tn, Gn2v, s_la[2] * tl2));
        e3 = exp2f(fmaf(-tn, Gn3,  s_la[3] * tl2));
        float sum = (e0 + e1) + (e2 + e3);
        float iv = __fdividef(1.0f, sum);
        f0 = e0 * iv; f1 = e1 * iv; f2 = e2 * iv; f3 = e3 * iv;
        float em = f0 * mj0;
        em = fmaf(f1, mj1, em);
        em = fmaf(f2, mj2, em);
        em = fmaf(f3, mj3, em);
        xt = em;
    }

    // ---------------- Write out: ft [B,NT,MC] then xt [B,NT] ----------------
    const size_t base = (size_t)b * NT + lane;
    float4 o;
    o.x = f0; o.y = f1; o.z = f2; o.w = f3;
    *reinterpret_cast<float4*>(&out[base * MC]) = o;
    out[(size_t)B * NT * MC + base] = xt;
}

extern "C" void kernel_launch(void* const* d_in, const int* in_sizes, int n_in,
                              void* d_out, int out_size)
{
    const float* yt     = (const float*)d_in[0];
    const float* Ht     = (const float*)d_in[1];
    const float* sig    = (const float*)d_in[2];
    const float* m      = (const float*)d_in[3];
    const float* alpha  = (const float*)d_in[4];
    const float* taui   = (const float*)d_in[5];
    const float* delta  = (const float*)d_in[6];

    const int B     = in_sizes[2];
    const int NR    = in_sizes[0] / B;
    const int NITER = in_sizes[6];

    const int blocks = (B + WARPS_PER_BLOCK - 1) / WARPS_PER_BLOCK;
    cmdnet_kernel<<<blocks, WARPS_PER_BLOCK * 32>>>(
        yt, Ht, sig, m, alpha, taui, delta, (float*)d_out, B, NR, NITER);
}

// round 15
// speedup vs baseline: 1.4755x; 1.0313x over previous
#include <cuda_runtime.h>
#include <cuda_bf16.h>

#define WARPS_PER_BLOCK 8
#define NT 32
#define MC 4
#define NITER_MAX 64
#define LOG2E 1.4426950408889634f

union f2u { float2 f; unsigned long long u; };

static __device__ __forceinline__ float2 fma2(float2 a, float2 b, float2 c) {
    f2u A, Bv, C, D; A.f = a; Bv.f = b; C.f = c;
    asm("fma.rn.f32x2 %0, %1, %2, %3;" : "=l"(D.u) : "l"(A.u), "l"(Bv.u), "l"(C.u));
    return D.f;
}
static __device__ __forceinline__ float2 mul2(float2 a, float2 b) {
    f2u A, Bv, D; A.f = a; Bv.f = b;
    asm("mul.rn.f32x2 %0, %1, %2;" : "=l"(D.u) : "l"(A.u), "l"(Bv.u));
    return D.f;
}
static __device__ __forceinline__ float2 add2(float2 a, float2 b) {
    f2u A, Bv, D; A.f = a; Bv.f = b;
    asm("add.rn.f32x2 %0, %1, %2;" : "=l"(D.u) : "l"(A.u), "l"(Bv.u));
    return D.f;
}
static __device__ __forceinline__ float rcp_fast(float x) {
    float r; asm("rcp.approx.f32 %0, %1;" : "=f"(r) : "f"(x)); return r;
}
// Single MUFU.EX2 — guaranteed, regardless of harness fast-math flags.
static __device__ __forceinline__ float ex2_fast(float x) {
    float r; asm("ex2.approx.f32 %0, %1;" : "=f"(r) : "f"(x)); return r;
}

// One warp per batch element. Quad-split HH ownership: lane (m = lane&7,
// q = lane>>3) holds cols [8q,8q+8) of rows {m,m+8,m+16,m+24} as 16 float2.
// Per-lane softmax state is for row = lane. xt broadcast via smem row + one
// syncwarp; acc returns via 2-stage reduce-scatter butterfly (3 SHFL).
// All hot-loop exponentials are ex2.approx -> single MUFU.EX2.
__global__ void __launch_bounds__(WARPS_PER_BLOCK * 32, 4)
cmdnet_kernel(const float* __restrict__ yt,
              const float* __restrict__ Ht,
              const float* __restrict__ sigmat0,
              const float* __restrict__ m_c,
              const float* __restrict__ alpha,
              const float* __restrict__ taui,
              const float* __restrict__ delta,
              float* __restrict__ out,
              int B, int NR, int NITER)
{
    __shared__ __align__(16) float4 s_lasc[NITER_MAX];  // la_j * scale_it * log2e
    __shared__ __align__(16) float4 s_p1[NITER_MAX];    // {-sc, -sc, -ta, d*log2e}
    __shared__ float s_la[MC];
    __shared__ float s_tauN, s_tauNl2;
    __shared__ __align__(16) float s_stage[WARPS_PER_BLOCK][2][NT];
    __shared__ __align__(16) float s_xt[2][WARPS_PER_BLOCK][NT];

    const int tid   = threadIdx.x;
    const int wslot = tid >> 5;
    const int lane  = tid & 31;
    const int m     = lane & 7;         // row-group member
    const int q     = lane >> 3;        // column-quad

    if (tid < NITER) {
        float ta = fabsf(taui[tid]);
        float scale_raw = (tid == 0) ? 1.0f : ta;     // first_iter softmax scale = 1
        float sc = scale_raw * LOG2E;
        float4 l;
        l.x = logf(alpha[0]) * sc;
        l.y = logf(alpha[1]) * sc;
        l.z = logf(alpha[2]) * sc;
        l.w = logf(alpha[3]) * sc;
        s_lasc[tid] = l;
        s_p1[tid] = make_float4(-scale_raw, -scale_raw, -ta, delta[tid] * LOG2E);
    }
    if (tid < MC) s_la[tid] = logf(alpha[tid]);
    if (tid == 0) {
        float tn = fabsf(taui[NITER]);
        s_tauN   = tn;
        s_tauNl2 = tn * LOG2E;
    }
    __syncthreads();

    const int b = blockIdx.x * WARPS_PER_BLOCK + wslot;
    if (b >= B) return;

    const float* Hb = Ht + (size_t)b * NR * NT;
    const float* yb = yt + (size_t)b * NR;

    // ---------------- Phase 1: quad-split HH + per-row yH ----------------
    // hhq[j][c] = HH[m+8j][8q+2c .. 8q+2c+1]
    float2 hhq[4][4];
    #pragma unroll
    for (int j = 0; j < 4; j++)
        #pragma unroll
        for (int c = 0; c < 4; c++) hhq[j][c] = make_float2(0.0f, 0.0f);
    float yH = 0.0f;

    for (int r0 = 0; r0 < NR; r0 += 2) {
        float h0 = Hb[(r0 + 0) * NT + lane];             // own column (coalesced)
        float h1 = Hb[(r0 + 1) * NT + lane];
        s_stage[wslot][0][lane] = h0;
        s_stage[wslot][1][lane] = h1;
        yH = fmaf(yb[r0 + 0], h0, yH);                   // row = lane
        yH = fmaf(yb[r0 + 1], h1, yH);
        __syncwarp();
        #pragma unroll
        for (int rr = 0; rr < 2; rr++) {
            float4 va = *reinterpret_cast<const float4*>(&s_stage[wslot][rr][8 * q]);
            float4 vb = *reinterpret_cast<const float4*>(&s_stage[wslot][rr][8 * q + 4]);
            #pragma unroll
            for (int j = 0; j < 4; j++) {
                float hr = s_stage[wslot][rr][m + 8 * j];
                const float2 h2 = make_float2(hr, hr);
                hhq[j][0] = fma2(h2, make_float2(va.x, va.y), hhq[j][0]);
                hhq[j][1] = fma2(h2, make_float2(va.z, va.w), hhq[j][1]);
                hhq[j][2] = fma2(h2, make_float2(vb.x, vb.y), hhq[j][2]);
                hhq[j][3] = fma2(h2, make_float2(vb.z, vb.w), hhq[j][3]);
            }
        }
        __syncwarp();
    }

    // ---------------- Phase 2: 64 iterations ----------------
    float2 m2[2];
    m2[0] = make_float2(m_c[0], m_c[1]);
    m2[1] = make_float2(m_c[2], m_c[3]);

    float2 Gn2[2] = {make_float2(0.f, 0.f), make_float2(0.f, 0.f)}; // -G*log2e
    float sig2;
    { float s = sigmat0[b]; sig2 = s * s; }
    const float2 sig2_2  = make_float2(sig2, sig2);
    const float2 nsig2_2 = make_float2(-sig2, -sig2);

    const bool qb0 = (q & 1) != 0;      // butterfly selectors
    const bool qb1 = (q & 2) != 0;

    float e0, e1, e2, e3;
    float inv = 0.0f, xt = 0.0f;

    #pragma unroll 2
    for (int it = 0; it < NITER; it++) {
        const float4 lasc = s_lasc[it];
        const float4 p    = s_p1[it];     // {-sc, -sc, -ta, d*log2e}
        const float2 sc2  = make_float2(p.x, p.y);
        const int buf = it & 1;

        // barrier term first (depends only on loop-carried Gn)
        const float2 eg0 = make_float2(ex2_fast(Gn2[0].x), ex2_fast(Gn2[0].y)); // exp(-G)
        const float2 eg1 = make_float2(ex2_fast(Gn2[1].x), ex2_fast(Gn2[1].y));
        float2 t0 = fma2(nsig2_2, eg0, sig2_2);
        float2 t1 = fma2(nsig2_2, eg1, sig2_2);

        // max-free softmax in log2 domain
        float2 z0 = fma2(sc2, Gn2[0], make_float2(lasc.x, lasc.y));
        float2 z1 = fma2(sc2, Gn2[1], make_float2(lasc.z, lasc.w));
        e0 = ex2_fast(z0.x); e1 = ex2_fast(z0.y);
        e2 = ex2_fast(z1.x); e3 = ex2_fast(z1.y);
        float sum = (e0 + e1) + (e2 + e3);
        inv = rcp_fast(sum);

        float em = e0 * m2[0].x;
        em = fmaf(e1, m2[0].y, em);
        em = fmaf(e2, m2[1].x, em);
        em = fmaf(e3, m2[1].y, em);
        xt = em * inv;                   // soft symbol for row = lane

        // share xt, then quad-split dot: 2 LDS.128 + 16 FFMA2 + butterfly
        s_xt[buf][wslot][lane] = xt;
        __syncwarp();
        float4 v0 = *reinterpret_cast<const float4*>(&s_xt[buf][wslot][8 * q]);
        float4 v1 = *reinterpret_cast<const float4*>(&s_xt[buf][wslot][8 * q + 4]);
        const float2 x0 = make_float2(v0.x, v0.y);
        const float2 x1 = make_float2(v0.z, v0.w);
        const float2 x2 = make_float2(v1.x, v1.y);
        const float2 x3 = make_float2(v1.z, v1.w);
        float P[4];
        #pragma unroll
        for (int j = 0; j < 4; j++) {
            float2 a = mul2(x0, hhq[j][0]);
            a = fma2(x1, hhq[j][1], a);
            a = fma2(x2, hhq[j][2], a);
            a = fma2(x3, hhq[j][3], a);
            P[j] = a.x + a.y;            // partial dot of row m+8j over my 8 cols
        }
        // reduce-scatter: stage 1 (xor 8) over q-bit0, stage 2 (xor 16) over q-bit1
        float give0 = qb0 ? P[0] : P[1];
        float give1 = qb0 ? P[2] : P[3];
        float keep0 = qb0 ? P[1] : P[0];
        float keep1 = qb0 ? P[3] : P[2];
        float S0 = keep0 + __shfl_xor_sync(0xFFFFFFFFu, give0, 8);  // row m+8*(q&1)
        float S1 = keep1 + __shfl_xor_sync(0xFFFFFFFFu, give1, 8);  // row m+16+8*(q&1)
        float give2 = qb1 ? S0 : S1;
        float keep2 = qb1 ? S1 : S0;
        float acc = keep2 + __shfl_xor_sync(0xFFFFFFFFu, give2, 16); // row = lane

        // grad_L_j = t_j + ci * e_j*(m_j - xt),  ci = ta*(xHH-yH)*inv
        const float c  = (yH - acc) * p.z;       // = ta*(acc - yH)
        const float ci = c * inv;
        const float2 ci2  = make_float2(ci, ci);
        const float2 dl2  = make_float2(p.w, p.w);
        const float2 nxt2 = make_float2(-xt, -xt);
        float2 d0 = add2(m2[0], nxt2);
        float2 d1 = add2(m2[1], nxt2);
        float2 w0 = mul2(make_float2(e0, e1), d0);
        float2 w1 = mul2(make_float2(e2, e3), d1);
        float2 g0 = fma2(ci2, w0, t0);
        float2 g1 = fma2(ci2, w1, t1);
        Gn2[0] = fma2(dl2, g0, Gn2[0]);
        Gn2[1] = fma2(dl2, g1, Gn2[1]);
    }

    // ---------------- Final layer: max-free softmax + soft symbol ------------
    float f[MC];
    {
        const float tl2 = s_tauNl2, tn = s_tauN;
        const float2 ntn2 = make_float2(-tn, -tn);
        float2 z0 = fma2(ntn2, Gn2[0], make_float2(s_la[0] * tl2, s_la[1] * tl2));
        float2 z1 = fma2(ntn2, Gn2[1], make_float2(s_la[2] * tl2, s_la[3] * tl2));
        e0 = ex2_fast(z0.x); e1 = ex2_fast(z0.y);
        e2 = ex2_fast(z1.x); e3 = ex2_fast(z1.y);
        float sum = (e0 + e1) + (e2 + e3);
        float iv = __fdividef(1.0f, sum);
        f[0] = e0 * iv; f[1] = e1 * iv; f[2] = e2 * iv; f[3] = e3 * iv;
        float em = f[0] * m2[0].x;
        em = fmaf(f[1], m2[0].y, em);
        em = fmaf(f[2], m2[1].x, em);
        em = fmaf(f[3], m2[1].y, em);
        xt = em;
    }

    // ---------------- Write out: ft [B,NT,MC] then xt [B,NT] ----------------
    const size_t base = (size_t)b * NT + lane;
    float4 o;
    o.x = f[0]; o.y = f[1]; o.z = f[2]; o.w = f[3];
    *reinterpret_cast<float4*>(&out[base * MC]) = o;
    out[(size_t)B * NT * MC + base] = xt;
}

extern "C" void kernel_launch(void* const* d_in, const int* in_sizes, int n_in,
                              void* d_out, int out_size)
{
    const float* yt     = (const float*)d_in[0];
    const float* Ht     = (const float*)d_in[1];
    const float* sig    = (const float*)d_in[2];
    const float* m      = (const float*)d_in[3];
    const float* alpha  = (const float*)d_in[4];
    const float* taui   = (const float*)d_in[5];
    const float* delta  = (const float*)d_in[6];

    const int B     = in_sizes[2];
    const int NR    = in_sizes[0] / B;
    const int NITER = in_sizes[6];

    const int blocks = (B + WARPS_PER_BLOCK - 1) / WARPS_PER_BLOCK;
    cmdnet_kernel<<<blocks, WARPS_PER_BLOCK * 32>>>(
        yt, Ht, sig, m, alpha, taui, delta, (float*)d_out, B, NR, NITER);
}